// round 9
// baseline (speedup 1.0000x reference)
#include <cuda_runtime.h>
#include <cuda_bf16.h>
#include <math.h>
#include <stdint.h>

#define NN 100000
#define GG 6000
#define EE 400000

// ---------------- scratch (device globals) ----------------
__device__ float g_q[(size_t)NN * 128];
__device__ float g_k[(size_t)GG * 128];
__device__ float g_val[(size_t)GG * 128];
__device__ float g_msn[(size_t)NN * 128];
__device__ float g_A[(size_t)NN * 128];
__device__ float g_B4[(size_t)NN * 128];
__device__ float g_mv[(size_t)NN * 384];

// ---------------- helpers ----------------
__device__ __forceinline__ void red_v4(float* addr, float4 v) {
    asm volatile("red.global.add.v4.f32 [%0], {%1,%2,%3,%4};"
                 :: "l"(addr), "f"(v.x), "f"(v.y), "f"(v.z), "f"(v.w) : "memory");
}
__device__ __forceinline__ void red_v2(float* addr, float x, float y) {
    asm volatile("red.global.add.v2.f32 [%0], {%1,%2};"
                 :: "l"(addr), "f"(x), "f"(y) : "memory");
}
__device__ __forceinline__ float silu_f(float x) { return x / (1.0f + expf(-x)); }

__device__ __forceinline__ uint32_t smem_u32(const void* p) {
    uint32_t a;
    asm("{ .reg .u64 t; cvta.to.shared.u64 t, %1; cvt.u32.u64 %0, t; }" : "=r"(a) : "l"(p));
    return a;
}
__device__ __forceinline__ void cpasync16(uint32_t dst, const void* src) {
    asm volatile("cp.async.cg.shared.global [%0], [%1], 16;" :: "r"(dst), "l"(src));
}
__device__ __forceinline__ void cp_commit() { asm volatile("cp.async.commit_group;" ::: "memory"); }
__device__ __forceinline__ void cp_wait1() { asm volatile("cp.async.wait_group 1;" ::: "memory"); }
__device__ __forceinline__ void cp_wait0() { asm volatile("cp.async.wait_group 0;" ::: "memory"); }

__device__ __forceinline__ void mma_bf16(float* d, const uint32_t* a, uint32_t b0, uint32_t b1) {
    asm volatile("mma.sync.aligned.m16n8k16.row.col.f32.bf16.bf16.f32 "
        "{%0,%1,%2,%3}, {%4,%5,%6,%7}, {%8,%9}, {%0,%1,%2,%3};"
        : "+f"(d[0]), "+f"(d[1]), "+f"(d[2]), "+f"(d[3])
        : "r"(a[0]), "r"(a[1]), "r"(a[2]), "r"(a[3]), "r"(b0), "r"(b1));
}

__device__ __forceinline__ void split2(float x, float y, uint32_t& h, uint32_t& l) {
    __nv_bfloat162 hh = __float22bfloat162_rn(make_float2(x, y));
    float2 hf = __bfloat1622float2(hh);
    __nv_bfloat162 ll = __float22bfloat162_rn(make_float2(x - hf.x, y - hf.y));
    h = *(uint32_t*)&hh;
    l = *(uint32_t*)&ll;
}

// ================= R5-config persistent GEMM (M=128 tiles, 512 thr) =================
template<bool DUAL, int MODE, int DBUF>
__global__ void __launch_bounds__(512, 1) gemm_mma(
    const float* __restrict__ X,
    const float* __restrict__ W1, const float* __restrict__ b1,
    const float* __restrict__ W2,
    float* __restrict__ Y1,
    const float* __restrict__ aux1, const float* __restrict__ aux2,
    int R)
{
    constexpr int AS = 136;
    constexpr int ND = DUAL ? 2 : 1;
    extern __shared__ float sm[];
    float* Abuf0 = sm;
    float* Abuf1 = sm + (DBUF == 2 ? 128 * AS : 0);
    __nv_bfloat16* Bb = (__nv_bfloat16*)(sm + DBUF * 128 * AS);

    const int t = threadIdx.x;
    const int lane = t & 31, wid = t >> 5;
    const int wm = wid & 3, wn = wid >> 2;
    const int nT = (R + 127) >> 7;

    {
        int r0 = blockIdx.x << 7;
        uint32_t base = smem_u32(Abuf0);
        #pragma unroll
        for (int i = 0; i < 8; i++) {
            int idx = t + i * 512;
            int row = idx >> 5, c = idx & 31;
            int gr = r0 + row; if (gr >= R) gr = R - 1;
            cpasync16(base + (uint32_t)(row * AS + c * 4) * 4, X + (size_t)gr * 128 + c * 4);
        }
        cp_commit();
    }

    #pragma unroll
    for (int w = 0; w < ND; w++) {
        const float* W = (w == 0) ? W1 : W2;
        __nv_bfloat16* BH = Bb + (size_t)w * 2 * 128 * AS;
        __nv_bfloat16* BL = BH + 128 * AS;
        for (int idx = t; idx < 128 * 128; idx += 512) {
            int n = idx & 127, k = idx >> 7;
            float v = W[k * 128 + n];
            __nv_bfloat16 h = __float2bfloat16(v);
            BH[n * AS + k] = h;
            BL[n * AS + k] = __float2bfloat16(v - __bfloat162float(h));
        }
    }

    int buf = 0;
    for (int tile = blockIdx.x; tile < nT; tile += gridDim.x) {
        int nt = tile + gridDim.x;
        if (DBUF == 2) {
            if (nt < nT) {
                int r0 = nt << 7;
                uint32_t base = smem_u32(buf ? Abuf0 : Abuf1);
                #pragma unroll
                for (int i = 0; i < 8; i++) {
                    int idx = t + i * 512;
                    int row = idx >> 5, c = idx & 31;
                    int gr = r0 + row; if (gr >= R) gr = R - 1;
                    cpasync16(base + (uint32_t)(row * AS + c * 4) * 4, X + (size_t)gr * 128 + c * 4);
                }
                cp_commit(); cp_wait1();
            } else {
                cp_wait0();
            }
        } else {
            cp_wait0();
        }
        __syncthreads();

        const float* Ac = (DBUF == 2 && buf) ? Abuf1 : Abuf0;

        float acc[ND][2][4][4];
        #pragma unroll
        for (int w = 0; w < ND; w++)
            #pragma unroll
            for (int mf = 0; mf < 2; mf++)
                #pragma unroll
                for (int j = 0; j < 4; j++)
                    #pragma unroll
                    for (int q = 0; q < 4; q++) acc[w][mf][j][q] = 0.f;

        const int rb = wm * 32 + (lane >> 2);
        const int klo = (lane & 3) * 2;

        #pragma unroll
        for (int ks = 0; ks < 8; ks++) {
            uint32_t ahi[2][4], alo[2][4];
            #pragma unroll
            for (int mf = 0; mf < 2; mf++) {
                #pragma unroll
                for (int q = 0; q < 4; q++) {
                    int row = rb + mf * 16 + (q & 1) * 8;
                    int kk = ks * 16 + klo + (q >> 1) * 8;
                    float2 v = *(const float2*)&Ac[row * AS + kk];
                    __nv_bfloat162 h = __float22bfloat162_rn(v);
                    float2 hf = __bfloat1622float2(h);
                    __nv_bfloat162 l = __float22bfloat162_rn(make_float2(v.x - hf.x, v.y - hf.y));
                    ahi[mf][q] = *(uint32_t*)&h;
                    alo[mf][q] = *(uint32_t*)&l;
                }
            }
            #pragma unroll
            for (int w = 0; w < ND; w++) {
                const __nv_bfloat16* BH = Bb + (size_t)w * 2 * 128 * AS;
                const __nv_bfloat16* BL = BH + 128 * AS;
                #pragma unroll
                for (int j = 0; j < 4; j++) {
                    int n = wn * 32 + j * 8 + (lane >> 2);
                    int kb = ks * 16 + klo;
                    uint32_t bh0 = *(const uint32_t*)&BH[n * AS + kb];
                    uint32_t bh1 = *(const uint32_t*)&BH[n * AS + kb + 8];
                    uint32_t bl0 = *(const uint32_t*)&BL[n * AS + kb];
                    uint32_t bl1 = *(const uint32_t*)&BL[n * AS + kb + 8];
                    #pragma unroll
                    for (int mf = 0; mf < 2; mf++) {
                        mma_bf16(acc[w][mf][j], ahi[mf], bh0, bh1);
                        mma_bf16(acc[w][mf][j], ahi[mf], bl0, bl1);
                        mma_bf16(acc[w][mf][j], alo[mf], bh0, bh1);
                    }
                }
            }
        }

        if (DBUF == 1) {
            __syncthreads();
            if (nt < nT) {
                int r0 = nt << 7;
                uint32_t base = smem_u32(Abuf0);
                #pragma unroll
                for (int i = 0; i < 8; i++) {
                    int idx = t + i * 512;
                    int row = idx >> 5, c = idx & 31;
                    int gr = r0 + row; if (gr >= R) gr = R - 1;
                    cpasync16(base + (uint32_t)(row * AS + c * 4) * 4, X + (size_t)gr * 128 + c * 4);
                }
                cp_commit();
            }
        }

        int r0t = tile << 7;
        #pragma unroll
        for (int mf = 0; mf < 2; mf++) {
            #pragma unroll
            for (int j = 0; j < 4; j++) {
                int cb = wn * 32 + j * 8 + (lane & 3) * 2;
                int row0 = r0t + wm * 32 + mf * 16 + (lane >> 2);
                int row1 = row0 + 8;
                if (MODE == 0) {
                    float bx = b1 ? b1[cb] : 0.f, by = b1 ? b1[cb + 1] : 0.f;
                    if (row0 < R)
                        *(float2*)&Y1[(size_t)row0 * 128 + cb] =
                            make_float2(acc[0][mf][j][0] + bx, acc[0][mf][j][1] + by);
                    if (row1 < R)
                        *(float2*)&Y1[(size_t)row1 * 128 + cb] =
                            make_float2(acc[0][mf][j][2] + bx, acc[0][mf][j][3] + by);
                } else if (MODE == 1) {
                    if (row0 < R) {
                        int n = row0 / 3;
                        float2 m = *(const float2*)&aux1[(size_t)row0 * 128 + cb];
                        float2 a = *(const float2*)&aux2[(size_t)n * 128 + cb];
                        *(float2*)&Y1[(size_t)row0 * 128 + cb] =
                            make_float2(m.x + a.x * acc[0][mf][j][0], m.y + a.y * acc[0][mf][j][1]);
                    }
                    if (row1 < R) {
                        int n = row1 / 3;
                        float2 m = *(const float2*)&aux1[(size_t)row1 * 128 + cb];
                        float2 a = *(const float2*)&aux2[(size_t)n * 128 + cb];
                        *(float2*)&Y1[(size_t)row1 * 128 + cb] =
                            make_float2(m.x + a.x * acc[0][mf][j][2], m.y + a.y * acc[0][mf][j][3]);
                    }
                } else {
                    if (row0 < R) {
                        int n = row0 / 3;
                        float2 b = *(const float2*)&aux2[(size_t)n * 128 + cb];
                        red_v2(&Y1[(size_t)n * 128 + cb],
                               acc[0][mf][j][0] * acc[1][mf][j][0] * b.x,
                               acc[0][mf][j][1] * acc[1][mf][j][1] * b.y);
                    }
                    if (row1 < R) {
                        int n = row1 / 3;
                        float2 b = *(const float2*)&aux2[(size_t)n * 128 + cb];
                        red_v2(&Y1[(size_t)n * 128 + cb],
                               acc[0][mf][j][2] * acc[1][mf][j][2] * b.x,
                               acc[0][mf][j][3] * acc[1][mf][j][3] * b.y);
                    }
                }
            }
        }
        if (DBUF == 2) { __syncthreads(); buf ^= 1; }
    }
}

// ================= 3-weight GEMM (measured 126us for msn triple) =================
__global__ void __launch_bounds__(256, 1) gemm3(
    const float* __restrict__ X,
    const float* __restrict__ W1, const float* __restrict__ W2, const float* __restrict__ W3,
    float* __restrict__ Y1, float* __restrict__ Y2, float* __restrict__ Y3,
    int R)
{
    constexpr int AS = 132;
    constexpr int WS = 132;
    extern __shared__ char smc[];
    float* Abuf = (float*)smc;
    __nv_bfloat16* Wb = (__nv_bfloat16*)(smc + 32 * AS * 4);

    const int t = threadIdx.x;
    const int lane = t & 31, wid = t >> 5;
    const int nT = (R + 31) >> 5;

    const float* Ws_[3] = { W1, W2, W3 };
    float* Ys_[3] = { Y1, Y2, Y3 };

    {
        int r0 = blockIdx.x << 5;
        uint32_t base = smem_u32(Abuf);
        #pragma unroll
        for (int i = 0; i < 4; i++) {
            int idx = t + i * 256;
            int row = idx >> 5, c = idx & 31;
            int gr = r0 + row; if (gr >= R) gr = R - 1;
            cpasync16(base + (uint32_t)(row * AS + c * 4) * 4, X + (size_t)gr * 128 + c * 4);
        }
        cp_commit();
    }

    #pragma unroll
    for (int w = 0; w < 3; w++) {
        __nv_bfloat16* WH = Wb + (size_t)w * 2 * 128 * WS;
        __nv_bfloat16* WL = WH + 128 * WS;
        for (int idx = t; idx < 128 * 128; idx += 256) {
            int n = idx & 127, k = idx >> 7;
            float v = Ws_[w][k * 128 + n];
            __nv_bfloat16 h = __float2bfloat16(v);
            WH[n * WS + k] = h;
            WL[n * WS + k] = __float2bfloat16(v - __bfloat162float(h));
        }
    }

    for (int tile = blockIdx.x; tile < nT; tile += gridDim.x) {
        cp_wait0();
        __syncthreads();

        float acc[3][2][2][4];
        #pragma unroll
        for (int w = 0; w < 3; w++)
            #pragma unroll
            for (int mf = 0; mf < 2; mf++)
                #pragma unroll
                for (int j = 0; j < 2; j++)
                    #pragma unroll
                    for (int q = 0; q < 4; q++) acc[w][mf][j][q] = 0.f;

        const int rb = lane >> 2;
        const int klo = (lane & 3) * 2;

        #pragma unroll
        for (int ks = 0; ks < 8; ks++) {
            uint32_t ahi[2][4], alo[2][4];
            #pragma unroll
            for (int mf = 0; mf < 2; mf++) {
                #pragma unroll
                for (int q = 0; q < 4; q++) {
                    int row = rb + mf * 16 + (q & 1) * 8;
                    int kk = ks * 16 + klo + (q >> 1) * 8;
                    float2 v = *(const float2*)&Abuf[row * AS + kk];
                    __nv_bfloat162 h = __float22bfloat162_rn(v);
                    float2 hf = __bfloat1622float2(h);
                    __nv_bfloat162 l = __float22bfloat162_rn(make_float2(v.x - hf.x, v.y - hf.y));
                    ahi[mf][q] = *(uint32_t*)&h;
                    alo[mf][q] = *(uint32_t*)&l;
                }
            }
            #pragma unroll
            for (int w = 0; w < 3; w++) {
                const __nv_bfloat16* WH = Wb + (size_t)w * 2 * 128 * WS;
                const __nv_bfloat16* WL = WH + 128 * WS;
                #pragma unroll
                for (int j = 0; j < 2; j++) {
                    int n = wid * 16 + j * 8 + (lane >> 2);
                    int kb = ks * 16 + klo;
                    uint32_t bh0 = *(const uint32_t*)&WH[n * WS + kb];
                    uint32_t bh1 = *(const uint32_t*)&WH[n * WS + kb + 8];
                    uint32_t bl0 = *(const uint32_t*)&WL[n * WS + kb];
                    uint32_t bl1 = *(const uint32_t*)&WL[n * WS + kb + 8];
                    #pragma unroll
                    for (int mf = 0; mf < 2; mf++) {
                        mma_bf16(acc[w][mf][j], ahi[mf], bh0, bh1);
                        mma_bf16(acc[w][mf][j], ahi[mf], bl0, bl1);
                        mma_bf16(acc[w][mf][j], alo[mf], bh0, bh1);
                    }
                }
            }
        }

        __syncthreads();
        int nt = tile + gridDim.x;
        if (nt < nT) {
            int r0 = nt << 5;
            uint32_t base = smem_u32(Abuf);
            #pragma unroll
            for (int i = 0; i < 4; i++) {
                int idx = t + i * 256;
                int row = idx >> 5, c = idx & 31;
                int gr = r0 + row; if (gr >= R) gr = R - 1;
                cpasync16(base + (uint32_t)(row * AS + c * 4) * 4, X + (size_t)gr * 128 + c * 4);
            }
            cp_commit();
        }

        int r0t = tile << 5;
        #pragma unroll
        for (int mf = 0; mf < 2; mf++) {
            #pragma unroll
            for (int j = 0; j < 2; j++) {
                int cb = wid * 16 + j * 8 + (lane & 3) * 2;
                int row0 = r0t + mf * 16 + (lane >> 2);
                #pragma unroll
                for (int w = 0; w < 3; w++) {
                    if (row0 < R)
                        *(float2*)&Ys_[w][(size_t)row0 * 128 + cb] =
                            make_float2(acc[w][mf][j][0], acc[w][mf][j][1]);
                    if (row0 + 8 < R)
                        *(float2*)&Ys_[w][(size_t)(row0 + 8) * 128 + cb] =
                            make_float2(acc[w][mf][j][2], acc[w][mf][j][3]);
                }
            }
        }
        __syncthreads();
    }
}

// ================= edge megakernel: 128-edge tiles, h overlays m_s =================
#define ETB 512
// staging region (73728 B): ms during gather/layer1, h after layer1
#define MS_HI   0
#define MS_LO   34816
#define H_PH    0
#define H_PL    18432
#define H_SH    36864
#define H_SL    55296
// weights
#define W1P_HI  73728
#define W1P_LO  91136
#define W1S_HI  108544
#define W1S_LO  125952
#define W2P_HI  143360
#define W2P_LO  161792
#define W2S_HI  180224
#define W2S_LO  198656
// misc
#define MK_NS   217088
#define MK_GS   217600
#define MK_US   218112
#define MK_BP1  219648
#define MK_BS1  219904
#define MK_BP2  220160
#define MK_BS2  220672
#define MEGA_SMEM 221184

__global__ void __launch_bounds__(ETB, 1) edge_mega(
    const int* __restrict__ node_idx, const int* __restrict__ group_idx,
    const float* __restrict__ edge_attr, const float* __restrict__ edge_vec,
    const float* __restrict__ group_vec,
    const float* __restrict__ Wp1, const float* __restrict__ bp1,
    const float* __restrict__ Wp2, const float* __restrict__ bp2,
    const float* __restrict__ Ws1, const float* __restrict__ bs1,
    const float* __restrict__ Ws2, const float* __restrict__ bs2)
{
    extern __shared__ char smc[];
    __nv_bfloat16* msHi = (__nv_bfloat16*)(smc + MS_HI);
    __nv_bfloat16* msLo = (__nv_bfloat16*)(smc + MS_LO);
    __nv_bfloat16* hPhi = (__nv_bfloat16*)(smc + H_PH);
    __nv_bfloat16* hPlo = (__nv_bfloat16*)(smc + H_PL);
    __nv_bfloat16* hShi = (__nv_bfloat16*)(smc + H_SH);
    __nv_bfloat16* hSlo = (__nv_bfloat16*)(smc + H_SL);
    __nv_bfloat16* w1pH = (__nv_bfloat16*)(smc + W1P_HI);
    __nv_bfloat16* w1pL = (__nv_bfloat16*)(smc + W1P_LO);
    __nv_bfloat16* w1sH = (__nv_bfloat16*)(smc + W1S_HI);
    __nv_bfloat16* w1sL = (__nv_bfloat16*)(smc + W1S_LO);
    __nv_bfloat16* w2pH = (__nv_bfloat16*)(smc + W2P_HI);
    __nv_bfloat16* w2pL = (__nv_bfloat16*)(smc + W2P_LO);
    __nv_bfloat16* w2sH = (__nv_bfloat16*)(smc + W2S_HI);
    __nv_bfloat16* w2sL = (__nv_bfloat16*)(smc + W2S_LO);
    int*   nS   = (int*)(smc + MK_NS);
    int*   gS   = (int*)(smc + MK_GS);
    float* uS   = (float*)(smc + MK_US);
    float* bp1s = (float*)(smc + MK_BP1);
    float* bs1s = (float*)(smc + MK_BS1);
    float* bp2s = (float*)(smc + MK_BP2);
    float* bs2s = (float*)(smc + MK_BS2);

    const int t = threadIdx.x;
    const int lane = t & 31, wid = t >> 5;
    const int wm = wid & 3, wn = wid >> 2;   // 16 warps: 4 m-stripes(32) x 4 n-stripes

    // resident weights
    for (int idx = t; idx < 64 * 128; idx += ETB) {
        int n = idx & 63, k = idx >> 6;
        float vp = Wp1[k * 64 + n], vs = Ws1[k * 64 + n];
        __nv_bfloat16 h = __float2bfloat16(vp);
        w1pH[n * 136 + k] = h;
        w1pL[n * 136 + k] = __float2bfloat16(vp - __bfloat162float(h));
        h = __float2bfloat16(vs);
        w1sH[n * 136 + k] = h;
        w1sL[n * 136 + k] = __float2bfloat16(vs - __bfloat162float(h));
    }
    for (int idx = t; idx < 128 * 64; idx += ETB) {
        int n = idx & 127, k = idx >> 7;
        float vp = Wp2[k * 128 + n], vs = Ws2[k * 128 + n];
        __nv_bfloat16 h = __float2bfloat16(vp);
        w2pH[n * 72 + k] = h;
        w2pL[n * 72 + k] = __float2bfloat16(vp - __bfloat162float(h));
        h = __float2bfloat16(vs);
        w2sH[n * 72 + k] = h;
        w2sL[n * 72 + k] = __float2bfloat16(vs - __bfloat162float(h));
    }
    if (t < 64)  { bp1s[t] = bp1[t]; bs1s[t] = bs1[t]; }
    if (t < 128) { bp2s[t] = bp2[t]; bs2s[t] = bs2[t]; }

    const int nTiles = EE / 128;
    for (int tile = blockIdx.x; tile < nTiles; tile += gridDim.x) {
        const int e0 = tile * 128;
        __syncthreads();   // previous tile fully consumed before ms overwrite

        // ---- gather + attention + m_s -> smem + msn red (4 thr/edge) ----
        {
            int r = t >> 2, sub = t & 3;
            int e = e0 + r;
            int n = node_idx[e], g = group_idx[e];
            if (sub == 0) { nS[r] = n; gS[r] = g; }
            if (t < 384) uS[t] = -edge_vec[(size_t)e0 * 3 + t];
            int c0 = sub * 32;
            float s0 = 0.f, s1 = 0.f;
            #pragma unroll
            for (int j = 0; j < 8; j++) {
                int c = c0 + j * 4;
                float4 q4 = *(const float4*)&g_q[(size_t)n * 128 + c];
                float4 k4 = *(const float4*)&g_k[(size_t)g * 128 + c];
                float4 a4 = *(const float4*)&edge_attr[(size_t)e * 128 + c];
                float p = q4.x * k4.x * a4.x + q4.y * k4.y * a4.y
                        + q4.z * k4.z * a4.z + q4.w * k4.w * a4.w;
                if (j < 4) s0 += p; else s1 += p;
            }
            float at0 = silu_f(s0 * 0.25f), at1 = silu_f(s1 * 0.25f);
            #pragma unroll
            for (int j = 0; j < 8; j++) {
                int c = c0 + j * 4;
                float a = (j < 4) ? at0 : at1;
                float4 v4 = *(const float4*)&g_val[(size_t)g * 128 + c];
                float4 m = make_float4(v4.x * a, v4.y * a, v4.z * a, v4.w * a);
                red_v4(&g_msn[(size_t)n * 128 + c], m);
                uint32_t h0, l0, h1, l1;
                split2(m.x, m.y, h0, l0);
                split2(m.z, m.w, h1, l1);
                int bidx = r * 136 + c;
                *(uint32_t*)&msHi[bidx] = h0;  *(uint32_t*)&msHi[bidx + 2] = h1;
                *(uint32_t*)&msLo[bidx] = l0;  *(uint32_t*)&msLo[bidx + 2] = l1;
            }
        }
        __syncthreads();

        // ---- layer 1: [128,128]@[128,64] dual -> acc in regs ----
        float accP[2][2][4], accS[2][2][4];
        #pragma unroll
        for (int mf = 0; mf < 2; mf++)
            #pragma unroll
            for (int j = 0; j < 2; j++)
                #pragma unroll
                for (int q = 0; q < 4; q++) { accP[mf][j][q] = 0.f; accS[mf][j][q] = 0.f; }
        {
            const int rB = wm * 32 + (lane >> 2);
            const int klo = (lane & 3) * 2;
            #pragma unroll
            for (int ks = 0; ks < 8; ks++) {
                uint32_t ahi[2][4], alo[2][4];
                #pragma unroll
                for (int mf = 0; mf < 2; mf++)
                    #pragma unroll
                    for (int q = 0; q < 4; q++) {
                        int row = rB + mf * 16 + (q & 1) * 8;
                        int kk = ks * 16 + klo + (q >> 1) * 8;
                        ahi[mf][q] = *(const uint32_t*)&msHi[row * 136 + kk];
                        alo[mf][q] = *(const uint32_t*)&msLo[row * 136 + kk];
                    }
                #pragma unroll
                for (int j = 0; j < 2; j++) {
                    int nIdx = wn * 16 + j * 8 + (lane >> 2);
                    int kb = ks * 16 + klo;
                    uint32_t ph0 = *(const uint32_t*)&w1pH[nIdx * 136 + kb];
                    uint32_t ph1 = *(const uint32_t*)&w1pH[nIdx * 136 + kb + 8];
                    uint32_t pl0 = *(const uint32_t*)&w1pL[nIdx * 136 + kb];
                    uint32_t pl1 = *(const uint32_t*)&w1pL[nIdx * 136 + kb + 8];
                    uint32_t sh0 = *(const uint32_t*)&w1sH[nIdx * 136 + kb];
                    uint32_t sh1 = *(const uint32_t*)&w1sH[nIdx * 136 + kb + 8];
                    uint32_t sl0 = *(const uint32_t*)&w1sL[nIdx * 136 + kb];
                    uint32_t sl1 = *(const uint32_t*)&w1sL[nIdx * 136 + kb + 8];
                    #pragma unroll
                    for (int mf = 0; mf < 2; mf++) {
                        mma_bf16(accP[mf][j], ahi[mf], ph0, ph1);
                        mma_bf16(accP[mf][j], ahi[mf], pl0, pl1);
                        mma_bf16(accP[mf][j], alo[mf], ph0, ph1);
                        mma_bf16(accS[mf][j], ahi[mf], sh0, sh1);
                        mma_bf16(accS[mf][j], ahi[mf], sl0, sl1);
                        mma_bf16(accS[mf][j], alo[mf], sh0, sh1);
                    }
                }
            }
        }
        __syncthreads();   // all ms reads complete before h overlays it

        // ---- silu + split -> h (overlaying ms region) ----
        {
            int cb = wn * 16 + (lane & 3) * 2;
            #pragma unroll
            for (int j = 0; j < 2; j++) {
                float b0p = bp1s[cb + j * 8], b1p = bp1s[cb + j * 8 + 1];
                float b0s = bs1s[cb + j * 8], b1s = bs1s[cb + j * 8 + 1];
                #pragma unroll
                for (int mf = 0; mf < 2; mf++) {
                    int row = wm * 32 + mf * 16 + (lane >> 2);
                    int cc = cb + j * 8;
                    uint32_t h, l;
                    split2(silu_f(accP[mf][j][0] + b0p), silu_f(accP[mf][j][1] + b1p), h, l);
                    *(uint32_t*)&hPhi[row * 72 + cc] = h;  *(uint32_t*)&hPlo[row * 72 + cc] = l;
                    split2(silu_f(accP[mf][j][2] + b0p), silu_f(accP[mf][j][3] + b1p), h, l);
                    *(uint32_t*)&hPhi[(row + 8) * 72 + cc] = h;  *(uint32_t*)&hPlo[(row + 8) * 72 + cc] = l;
                    split2(silu_f(accS[mf][j][0] + b0s), silu_f(accS[mf][j][1] + b1s), h, l);
                    *(uint32_t*)&hShi[row * 72 + cc] = h;  *(uint32_t*)&hSlo[row * 72 + cc] = l;
                    split2(silu_f(accS[mf][j][2] + b0s), silu_f(accS[mf][j][3] + b1s), h, l);
                    *(uint32_t*)&hShi[(row + 8) * 72 + cc] = h;  *(uint32_t*)&hSlo[(row + 8) * 72 + cc] = l;
                }
            }
        }
        __syncthreads();

        // ---- layer 2 + fragment scatter, two n-chunks of 16 cols ----
        const int rB = wm * 32 + (lane >> 2);
        const int klo = (lane & 3) * 2;
        #pragma unroll
        for (int nh = 0; nh < 2; nh++) {
            float a2P[2][2][4], a2S[2][2][4];
            #pragma unroll
            for (int mf = 0; mf < 2; mf++)
                #pragma unroll
                for (int j = 0; j < 2; j++)
                    #pragma unroll
                    for (int q = 0; q < 4; q++) { a2P[mf][j][q] = 0.f; a2S[mf][j][q] = 0.f; }
            #pragma unroll
            for (int ks = 0; ks < 4; ks++) {
                uint32_t aPh[2][4], aPl[2][4], aSh[2][4], aSl[2][4];
                #pragma unroll
                for (int mf = 0; mf < 2; mf++)
                    #pragma unroll
                    for (int q = 0; q < 4; q++) {
                        int row = rB + mf * 16 + (q & 1) * 8;
                        int kk = ks * 16 + klo + (q >> 1) * 8;
                        int off = row * 72 + kk;
                        aPh[mf][q] = *(const uint32_t*)&hPhi[off];
                        aPl[mf][q] = *(const uint32_t*)&hPlo[off];
                        aSh[mf][q] = *(const uint32_t*)&hShi[off];
                        aSl[mf][q] = *(const uint32_t*)&hSlo[off];
                    }
                #pragma unroll
                for (int j = 0; j < 2; j++) {
                    int nIdx = wn * 32 + nh * 16 + j * 8 + (lane >> 2);
                    int kb = ks * 16 + klo;
                    uint32_t ph0 = *(const uint32_t*)&w2pH[nIdx * 72 + kb];
                    uint32_t ph1 = *(const uint32_t*)&w2pH[nIdx * 72 + kb + 8];
                    uint32_t pl0 = *(const uint32_t*)&w2pL[nIdx * 72 + kb];
                    uint32_t pl1 = *(const uint32_t*)&w2pL[nIdx * 72 + kb + 8];
                    uint32_t sh0 = *(const uint32_t*)&w2sH[nIdx * 72 + kb];
                    uint32_t sh1 = *(const uint32_t*)&w2sH[nIdx * 72 + kb + 8];
                    uint32_t sl0 = *(const uint32_t*)&w2sL[nIdx * 72 + kb];
                    uint32_t sl1 = *(const uint32_t*)&w2sL[nIdx * 72 + kb + 8];
                    #pragma unroll
                    for (int mf = 0; mf < 2; mf++) {
                        mma_bf16(a2P[mf][j], aPh[mf], ph0, ph1);
                        mma_bf16(a2P[mf][j], aPh[mf], pl0, pl1);
                        mma_bf16(a2P[mf][j], aPl[mf], ph0, ph1);
                        mma_bf16(a2S[mf][j], aSh[mf], sh0, sh1);
                        mma_bf16(a2S[mf][j], aSh[mf], sl0, sl1);
                        mma_bf16(a2S[mf][j], aSl[mf], sh0, sh1);
                    }
                }
            }
            // scatter this chunk from fragments
            #pragma unroll
            for (int mf = 0; mf < 2; mf++) {
                #pragma unroll
                for (int j = 0; j < 2; j++) {
                    int cb = wn * 32 + nh * 16 + j * 8 + (lane & 3) * 2;
                    float b0p = bp2s[cb], b1p = bp2s[cb + 1];
                    float b0s = bs2s[cb], b1s = bs2s[cb + 1];
                    #pragma unroll
                    for (int half = 0; half < 2; half++) {
                        int row = wm * 32 + mf * 16 + (lane >> 2) + half * 8;
                        float spx = a2P[mf][j][half * 2 + 0] + b0p;
                        float spy = a2P[mf][j][half * 2 + 1] + b1p;
                        float svx = a2S[mf][j][half * 2 + 0] + b0s;
                        float svy = a2S[mf][j][half * 2 + 1] + b1s;
                        int n = nS[row], g = gS[row];
                        #pragma unroll
                        for (int d = 0; d < 3; d++) {
                            float u = uS[row * 3 + d];
                            float2 gv = *(const float2*)&group_vec[((size_t)g * 3 + d) * 128 + cb];
                            red_v2(&g_mv[((size_t)n * 3 + d) * 128 + cb],
                                   spx * u + svx * gv.x, spy * u + svy * gv.y);
                        }
                    }
                }
            }
        }
    }
}

// ---------------- launch ----------------
static inline int gsz(int R) { int nT = (R + 127) >> 7; return nT < 148 ? nT : 148; }
static inline int gsz32(int R) { int nT = (R + 31) >> 5; return nT < 148 ? nT : 148; }

extern "C" void kernel_launch(void* const* d_in, const int* in_sizes, int n_in,
                              void* d_out, int out_size) {
    const int*   node_idx        = (const int*)d_in[0];
    const int*   group_idx       = (const int*)d_in[1];
    const float* node_embedding  = (const float*)d_in[2];
    const float* node_vec        = (const float*)d_in[3];
    const float* group_embedding = (const float*)d_in[4];
    const float* group_vec       = (const float*)d_in[5];
    const float* edge_attr       = (const float*)d_in[6];
    const float* edge_vec        = (const float*)d_in[8];
    const float* Wq  = (const float*)d_in[9];  const float* bq  = (const float*)d_in[10];
    const float* Wk  = (const float*)d_in[11]; const float* bk  = (const float*)d_in[12];
    const float* Wvl = (const float*)d_in[13]; const float* bvl = (const float*)d_in[14];
    const float* Wp1 = (const float*)d_in[15]; const float* bp1 = (const float*)d_in[16];
    const float* Wp2 = (const float*)d_in[17]; const float* bp2 = (const float*)d_in[18];
    const float* Ws1 = (const float*)d_in[19]; const float* bs1 = (const float*)d_in[20];
    const float* Ws2 = (const float*)d_in[21]; const float* bs2 = (const float*)d_in[22];
    const float* L0  = (const float*)d_in[23];
    const float* L1  = (const float*)d_in[24];
    const float* L2  = (const float*)d_in[25];
    const float* L3  = (const float*)d_in[26];
    const float* L4  = (const float*)d_in[27];
    const float* L5  = (const float*)d_in[28];

    float* dx = (float*)d_out;
    float* dv = (float*)d_out + (size_t)NN * 128;

    const int SM_G  = 208896;
    const int SM_G3 = 16896 + 3 * 67584;
    cudaFuncSetAttribute(gemm_mma<false, 0, 2>, cudaFuncAttributeMaxDynamicSharedMemorySize, SM_G);
    cudaFuncSetAttribute(gemm_mma<false, 1, 2>, cudaFuncAttributeMaxDynamicSharedMemorySize, SM_G);
    cudaFuncSetAttribute(gemm_mma<true, 2, 1>,  cudaFuncAttributeMaxDynamicSharedMemorySize, SM_G);
    cudaFuncSetAttribute(gemm3, cudaFuncAttributeMaxDynamicSharedMemorySize, SM_G3);
    cudaFuncSetAttribute(edge_mega, cudaFuncAttributeMaxDynamicSharedMemorySize, MEGA_SMEM);

    float *p_q, *p_k, *p_val, *p_msn, *p_A, *p_B, *p_mv;
    cudaGetSymbolAddress((void**)&p_q, g_q);
    cudaGetSymbolAddress((void**)&p_k, g_k);
    cudaGetSymbolAddress((void**)&p_val, g_val);
    cudaGetSymbolAddress((void**)&p_msn, g_msn);
    cudaGetSymbolAddress((void**)&p_A, g_A);
    cudaGetSymbolAddress((void**)&p_B, g_B4);
    cudaGetSymbolAddress((void**)&p_mv, g_mv);

    cudaMemsetAsync(p_msn, 0, sizeof(float) * (size_t)NN * 128, 0);
    cudaMemsetAsync(p_mv,  0, sizeof(float) * (size_t)NN * 384, 0);

    // q / k / val
    gemm_mma<false, 0, 2><<<gsz(NN), 512, SM_G>>>(node_embedding, Wq, bq, nullptr, p_q, nullptr, nullptr, NN);
    gemm_mma<false, 0, 2><<<gsz(GG), 512, SM_G>>>(group_embedding, Wk, bk, nullptr, p_k, nullptr, nullptr, GG);
    gemm_mma<false, 0, 2><<<gsz(GG), 512, SM_G>>>(group_embedding, Wvl, bvl, nullptr, p_val, nullptr, nullptr, GG);

    // fused edge pipeline (128-edge tiles)
    edge_mega<<<148, ETB, MEGA_SMEM>>>(node_idx, group_idx, edge_attr, edge_vec, group_vec,
                                       Wp1, bp1, Wp2, bp2, Ws1, bs1, Ws2, bs2);

    // node-side triple: A = msn@L0, B = msn@L4, dx = msn@L5
    gemm3<<<gsz32(NN), 256, SM_G3>>>(p_msn, L0, L4, L5, p_A, p_B, dx, NN);

    // dv = g_mv + A[n] * (nv@L1)
    gemm_mma<false, 1, 2><<<gsz(3 * NN), 512, SM_G>>>(node_vec, L1, nullptr, nullptr, dv, p_mv, p_A, 3 * NN);

    // dx += sum_d (nv@L2)*(nv@L3)*B[n]
    gemm_mma<true, 2, 1><<<gsz(3 * NN), 512, SM_G>>>(node_vec, L2, nullptr, L3, dx, nullptr, p_B, 3 * NN);
}

// round 10
// speedup vs baseline: 1.3238x; 1.3238x over previous
#include <cuda_runtime.h>
#include <cuda_bf16.h>
#include <math.h>
#include <stdint.h>

#define NN 100000
#define GG 6000
#define EE 400000

// ---------------- scratch (device globals) ----------------
__device__ float g_q[(size_t)NN * 128];
__device__ float g_k[(size_t)GG * 128];
__device__ float g_val[(size_t)GG * 128];
__device__ float g_msn[(size_t)NN * 128];
__device__ float g_A[(size_t)NN * 128];
__device__ float g_B4[(size_t)NN * 128];
__device__ float g_mv[(size_t)NN * 384];

// ---------------- helpers ----------------
__device__ __forceinline__ void red_v4(float* addr, float4 v) {
    asm volatile("red.global.add.v4.f32 [%0], {%1,%2,%3,%4};"
                 :: "l"(addr), "f"(v.x), "f"(v.y), "f"(v.z), "f"(v.w) : "memory");
}
__device__ __forceinline__ void red_v2(float* addr, float x, float y) {
    asm volatile("red.global.add.v2.f32 [%0], {%1,%2};"
                 :: "l"(addr), "f"(x), "f"(y) : "memory");
}
__device__ __forceinline__ float silu_f(float x) { return x / (1.0f + expf(-x)); }

__device__ __forceinline__ uint32_t smem_u32(const void* p) {
    uint32_t a;
    asm("{ .reg .u64 t; cvta.to.shared.u64 t, %1; cvt.u32.u64 %0, t; }" : "=r"(a) : "l"(p));
    return a;
}
__device__ __forceinline__ void cpasync16(uint32_t dst, const void* src) {
    asm volatile("cp.async.cg.shared.global [%0], [%1], 16;" :: "r"(dst), "l"(src));
}
__device__ __forceinline__ void cp_commit() { asm volatile("cp.async.commit_group;" ::: "memory"); }
__device__ __forceinline__ void cp_wait1() { asm volatile("cp.async.wait_group 1;" ::: "memory"); }
__device__ __forceinline__ void cp_wait0() { asm volatile("cp.async.wait_group 0;" ::: "memory"); }

__device__ __forceinline__ void mma_bf16(float* d, const uint32_t* a, uint32_t b0, uint32_t b1) {
    asm volatile("mma.sync.aligned.m16n8k16.row.col.f32.bf16.bf16.f32 "
        "{%0,%1,%2,%3}, {%4,%5,%6,%7}, {%8,%9}, {%0,%1,%2,%3};"
        : "+f"(d[0]), "+f"(d[1]), "+f"(d[2]), "+f"(d[3])
        : "r"(a[0]), "r"(a[1]), "r"(a[2]), "r"(a[3]), "r"(b0), "r"(b1));
}

__device__ __forceinline__ void split2(float x, float y, uint32_t& h, uint32_t& l) {
    __nv_bfloat162 hh = __float22bfloat162_rn(make_float2(x, y));
    float2 hf = __bfloat1622float2(hh);
    __nv_bfloat162 ll = __float22bfloat162_rn(make_float2(x - hf.x, y - hf.y));
    h = *(uint32_t*)&hh;
    l = *(uint32_t*)&ll;
}

// ================= R5-config persistent GEMM (M=128 tiles, 512 thr) =================
template<bool DUAL, int MODE, int DBUF>
__global__ void __launch_bounds__(512, 1) gemm_mma(
    const float* __restrict__ X,
    const float* __restrict__ W1, const float* __restrict__ b1,
    const float* __restrict__ W2,
    float* __restrict__ Y1,
    const float* __restrict__ aux1, const float* __restrict__ aux2,
    int R)
{
    constexpr int AS = 136;
    constexpr int ND = DUAL ? 2 : 1;
    extern __shared__ float sm[];
    float* Abuf0 = sm;
    float* Abuf1 = sm + (DBUF == 2 ? 128 * AS : 0);
    __nv_bfloat16* Bb = (__nv_bfloat16*)(sm + DBUF * 128 * AS);

    const int t = threadIdx.x;
    const int lane = t & 31, wid = t >> 5;
    const int wm = wid & 3, wn = wid >> 2;
    const int nT = (R + 127) >> 7;

    {
        int r0 = blockIdx.x << 7;
        uint32_t base = smem_u32(Abuf0);
        #pragma unroll
        for (int i = 0; i < 8; i++) {
            int idx = t + i * 512;
            int row = idx >> 5, c = idx & 31;
            int gr = r0 + row; if (gr >= R) gr = R - 1;
            cpasync16(base + (uint32_t)(row * AS + c * 4) * 4, X + (size_t)gr * 128 + c * 4);
        }
        cp_commit();
    }

    #pragma unroll
    for (int w = 0; w < ND; w++) {
        const float* W = (w == 0) ? W1 : W2;
        __nv_bfloat16* BH = Bb + (size_t)w * 2 * 128 * AS;
        __nv_bfloat16* BL = BH + 128 * AS;
        for (int idx = t; idx < 128 * 128; idx += 512) {
            int n = idx & 127, k = idx >> 7;
            float v = W[k * 128 + n];
            __nv_bfloat16 h = __float2bfloat16(v);
            BH[n * AS + k] = h;
            BL[n * AS + k] = __float2bfloat16(v - __bfloat162float(h));
        }
    }

    int buf = 0;
    for (int tile = blockIdx.x; tile < nT; tile += gridDim.x) {
        int nt = tile + gridDim.x;
        if (DBUF == 2) {
            if (nt < nT) {
                int r0 = nt << 7;
                uint32_t base = smem_u32(buf ? Abuf0 : Abuf1);
                #pragma unroll
                for (int i = 0; i < 8; i++) {
                    int idx = t + i * 512;
                    int row = idx >> 5, c = idx & 31;
                    int gr = r0 + row; if (gr >= R) gr = R - 1;
                    cpasync16(base + (uint32_t)(row * AS + c * 4) * 4, X + (size_t)gr * 128 + c * 4);
                }
                cp_commit(); cp_wait1();
            } else {
                cp_wait0();
            }
        } else {
            cp_wait0();
        }
        __syncthreads();

        const float* Ac = (DBUF == 2 && buf) ? Abuf1 : Abuf0;

        float acc[ND][2][4][4];
        #pragma unroll
        for (int w = 0; w < ND; w++)
            #pragma unroll
            for (int mf = 0; mf < 2; mf++)
                #pragma unroll
                for (int j = 0; j < 4; j++)
                    #pragma unroll
                    for (int q = 0; q < 4; q++) acc[w][mf][j][q] = 0.f;

        const int rb = wm * 32 + (lane >> 2);
        const int klo = (lane & 3) * 2;

        #pragma unroll
        for (int ks = 0; ks < 8; ks++) {
            uint32_t ahi[2][4], alo[2][4];
            #pragma unroll
            for (int mf = 0; mf < 2; mf++) {
                #pragma unroll
                for (int q = 0; q < 4; q++) {
                    int row = rb + mf * 16 + (q & 1) * 8;
                    int kk = ks * 16 + klo + (q >> 1) * 8;
                    float2 v = *(const float2*)&Ac[row * AS + kk];
                    __nv_bfloat162 h = __float22bfloat162_rn(v);
                    float2 hf = __bfloat1622float2(h);
                    __nv_bfloat162 l = __float22bfloat162_rn(make_float2(v.x - hf.x, v.y - hf.y));
                    ahi[mf][q] = *(uint32_t*)&h;
                    alo[mf][q] = *(uint32_t*)&l;
                }
            }
            #pragma unroll
            for (int w = 0; w < ND; w++) {
                const __nv_bfloat16* BH = Bb + (size_t)w * 2 * 128 * AS;
                const __nv_bfloat16* BL = BH + 128 * AS;
                #pragma unroll
                for (int j = 0; j < 4; j++) {
                    int n = wn * 32 + j * 8 + (lane >> 2);
                    int kb = ks * 16 + klo;
                    uint32_t bh0 = *(const uint32_t*)&BH[n * AS + kb];
                    uint32_t bh1 = *(const uint32_t*)&BH[n * AS + kb + 8];
                    uint32_t bl0 = *(const uint32_t*)&BL[n * AS + kb];
                    uint32_t bl1 = *(const uint32_t*)&BL[n * AS + kb + 8];
                    #pragma unroll
                    for (int mf = 0; mf < 2; mf++) {
                        mma_bf16(acc[w][mf][j], ahi[mf], bh0, bh1);
                        mma_bf16(acc[w][mf][j], ahi[mf], bl0, bl1);
                        mma_bf16(acc[w][mf][j], alo[mf], bh0, bh1);
                    }
                }
            }
        }

        if (DBUF == 1) {
            __syncthreads();
            if (nt < nT) {
                int r0 = nt << 7;
                uint32_t base = smem_u32(Abuf0);
                #pragma unroll
                for (int i = 0; i < 8; i++) {
                    int idx = t + i * 512;
                    int row = idx >> 5, c = idx & 31;
                    int gr = r0 + row; if (gr >= R) gr = R - 1;
                    cpasync16(base + (uint32_t)(row * AS + c * 4) * 4, X + (size_t)gr * 128 + c * 4);
                }
                cp_commit();
            }
        }

        int r0t = tile << 7;
        #pragma unroll
        for (int mf = 0; mf < 2; mf++) {
            #pragma unroll
            for (int j = 0; j < 4; j++) {
                int cb = wn * 32 + j * 8 + (lane & 3) * 2;
                int row0 = r0t + wm * 32 + mf * 16 + (lane >> 2);
                int row1 = row0 + 8;
                if (MODE == 0) {
                    float bx = b1 ? b1[cb] : 0.f, by = b1 ? b1[cb + 1] : 0.f;
                    if (row0 < R)
                        *(float2*)&Y1[(size_t)row0 * 128 + cb] =
                            make_float2(acc[0][mf][j][0] + bx, acc[0][mf][j][1] + by);
                    if (row1 < R)
                        *(float2*)&Y1[(size_t)row1 * 128 + cb] =
                            make_float2(acc[0][mf][j][2] + bx, acc[0][mf][j][3] + by);
                } else if (MODE == 1) {
                    if (row0 < R) {
                        int n = row0 / 3;
                        float2 m = *(const float2*)&aux1[(size_t)row0 * 128 + cb];
                        float2 a = *(const float2*)&aux2[(size_t)n * 128 + cb];
                        *(float2*)&Y1[(size_t)row0 * 128 + cb] =
                            make_float2(m.x + a.x * acc[0][mf][j][0], m.y + a.y * acc[0][mf][j][1]);
                    }
                    if (row1 < R) {
                        int n = row1 / 3;
                        float2 m = *(const float2*)&aux1[(size_t)row1 * 128 + cb];
                        float2 a = *(const float2*)&aux2[(size_t)n * 128 + cb];
                        *(float2*)&Y1[(size_t)row1 * 128 + cb] =
                            make_float2(m.x + a.x * acc[0][mf][j][2], m.y + a.y * acc[0][mf][j][3]);
                    }
                } else {
                    if (row0 < R) {
                        int n = row0 / 3;
                        float2 b = *(const float2*)&aux2[(size_t)n * 128 + cb];
                        red_v2(&Y1[(size_t)n * 128 + cb],
                               acc[0][mf][j][0] * acc[1][mf][j][0] * b.x,
                               acc[0][mf][j][1] * acc[1][mf][j][1] * b.y);
                    }
                    if (row1 < R) {
                        int n = row1 / 3;
                        float2 b = *(const float2*)&aux2[(size_t)n * 128 + cb];
                        red_v2(&Y1[(size_t)n * 128 + cb],
                               acc[0][mf][j][2] * acc[1][mf][j][2] * b.x,
                               acc[0][mf][j][3] * acc[1][mf][j][3] * b.y);
                    }
                }
            }
        }
        if (DBUF == 2) { __syncthreads(); buf ^= 1; }
    }
}

// ================= multi-weight M=32 GEMM (gemm3 pattern) =================
// NW weights resident; optional biases. Measured 126us for the msn triple.
template<int NW>
__global__ void __launch_bounds__(256, 1) gemmNW(
    const float* __restrict__ X,
    const float* __restrict__ W1, const float* __restrict__ W2, const float* __restrict__ W3,
    const float* __restrict__ b1, const float* __restrict__ b2, const float* __restrict__ b3,
    float* __restrict__ Y1, float* __restrict__ Y2, float* __restrict__ Y3,
    int R)
{
    constexpr int AS = 132;
    constexpr int WS = 132;
    extern __shared__ char smc[];
    float* Abuf = (float*)smc;
    __nv_bfloat16* Wb = (__nv_bfloat16*)(smc + 32 * AS * 4);

    const int t = threadIdx.x;
    const int lane = t & 31, wid = t >> 5;
    const int nT = (R + 31) >> 5;

    const float* Ws_[3] = { W1, W2, W3 };
    const float* bs_[3] = { b1, b2, b3 };
    float* Ys_[3] = { Y1, Y2, Y3 };

    {
        int r0 = blockIdx.x << 5;
        uint32_t base = smem_u32(Abuf);
        #pragma unroll
        for (int i = 0; i < 4; i++) {
            int idx = t + i * 256;
            int row = idx >> 5, c = idx & 31;
            int gr = r0 + row; if (gr >= R) gr = R - 1;
            cpasync16(base + (uint32_t)(row * AS + c * 4) * 4, X + (size_t)gr * 128 + c * 4);
        }
        cp_commit();
    }

    #pragma unroll
    for (int w = 0; w < NW; w++) {
        __nv_bfloat16* WH = Wb + (size_t)w * 2 * 128 * WS;
        __nv_bfloat16* WL = WH + 128 * WS;
        for (int idx = t; idx < 128 * 128; idx += 256) {
            int n = idx & 127, k = idx >> 7;
            float v = Ws_[w][k * 128 + n];
            __nv_bfloat16 h = __float2bfloat16(v);
            WH[n * WS + k] = h;
            WL[n * WS + k] = __float2bfloat16(v - __bfloat162float(h));
        }
    }

    for (int tile = blockIdx.x; tile < nT; tile += gridDim.x) {
        cp_wait0();
        __syncthreads();

        float acc[NW][2][2][4];
        #pragma unroll
        for (int w = 0; w < NW; w++)
            #pragma unroll
            for (int mf = 0; mf < 2; mf++)
                #pragma unroll
                for (int j = 0; j < 2; j++)
                    #pragma unroll
                    for (int q = 0; q < 4; q++) acc[w][mf][j][q] = 0.f;

        const int rb = lane >> 2;
        const int klo = (lane & 3) * 2;

        #pragma unroll
        for (int ks = 0; ks < 8; ks++) {
            uint32_t ahi[2][4], alo[2][4];
            #pragma unroll
            for (int mf = 0; mf < 2; mf++) {
                #pragma unroll
                for (int q = 0; q < 4; q++) {
                    int row = rb + mf * 16 + (q & 1) * 8;
                    int kk = ks * 16 + klo + (q >> 1) * 8;
                    float2 v = *(const float2*)&Abuf[row * AS + kk];
                    __nv_bfloat162 h = __float22bfloat162_rn(v);
                    float2 hf = __bfloat1622float2(h);
                    __nv_bfloat162 l = __float22bfloat162_rn(make_float2(v.x - hf.x, v.y - hf.y));
                    ahi[mf][q] = *(uint32_t*)&h;
                    alo[mf][q] = *(uint32_t*)&l;
                }
            }
            #pragma unroll
            for (int w = 0; w < NW; w++) {
                const __nv_bfloat16* WH = Wb + (size_t)w * 2 * 128 * WS;
                const __nv_bfloat16* WL = WH + 128 * WS;
                #pragma unroll
                for (int j = 0; j < 2; j++) {
                    int n = wid * 16 + j * 8 + (lane >> 2);
                    int kb = ks * 16 + klo;
                    uint32_t bh0 = *(const uint32_t*)&WH[n * WS + kb];
                    uint32_t bh1 = *(const uint32_t*)&WH[n * WS + kb + 8];
                    uint32_t bl0 = *(const uint32_t*)&WL[n * WS + kb];
                    uint32_t bl1 = *(const uint32_t*)&WL[n * WS + kb + 8];
                    #pragma unroll
                    for (int mf = 0; mf < 2; mf++) {
                        mma_bf16(acc[w][mf][j], ahi[mf], bh0, bh1);
                        mma_bf16(acc[w][mf][j], ahi[mf], bl0, bl1);
                        mma_bf16(acc[w][mf][j], alo[mf], bh0, bh1);
                    }
                }
            }
        }

        __syncthreads();
        int nt = tile + gridDim.x;
        if (nt < nT) {
            int r0 = nt << 5;
            uint32_t base = smem_u32(Abuf);
            #pragma unroll
            for (int i = 0; i < 4; i++) {
                int idx = t + i * 256;
                int row = idx >> 5, c = idx & 31;
                int gr = r0 + row; if (gr >= R) gr = R - 1;
                cpasync16(base + (uint32_t)(row * AS + c * 4) * 4, X + (size_t)gr * 128 + c * 4);
            }
            cp_commit();
        }

        int r0t = tile << 5;
        #pragma unroll
        for (int mf = 0; mf < 2; mf++) {
            #pragma unroll
            for (int j = 0; j < 2; j++) {
                int cb = wid * 16 + j * 8 + (lane & 3) * 2;
                int row0 = r0t + mf * 16 + (lane >> 2);
                #pragma unroll
                for (int w = 0; w < NW; w++) {
                    float bx = bs_[w] ? bs_[w][cb] : 0.f;
                    float by = bs_[w] ? bs_[w][cb + 1] : 0.f;
                    if (row0 < R)
                        *(float2*)&Ys_[w][(size_t)row0 * 128 + cb] =
                            make_float2(acc[w][mf][j][0] + bx, acc[w][mf][j][1] + by);
                    if (row0 + 8 < R)
                        *(float2*)&Ys_[w][(size_t)(row0 + 8) * 128 + cb] =
                            make_float2(acc[w][mf][j][2] + bx, acc[w][mf][j][3] + by);
                }
            }
        }
        __syncthreads();
    }
}

// ================= edge megakernel (R5-exact, measured 663-668us) =================
#define ETB 512
#define MS_HI   0
#define MS_LO   17408
#define HP_HI   34816
#define HP_LO   44032
#define HS_HI   53248
#define HS_LO   62464
#define W1P_HI  71680
#define W1P_LO  89088
#define W1S_HI  106496
#define W1S_LO  123904
#define W2P_HI  141312
#define W2P_LO  159744
#define W2S_HI  178176
#define W2S_LO  196608
#define MK_NS   215040
#define MK_GS   215296
#define MK_US   215552
#define MK_BP1  216320
#define MK_BS1  216576
#define MK_BP2  216832
#define MK_BS2  217344
#define MEGA_SMEM 217856

__global__ void __launch_bounds__(ETB, 1) edge_mega(
    const int* __restrict__ node_idx, const int* __restrict__ group_idx,
    const float* __restrict__ edge_attr, const float* __restrict__ edge_vec,
    const float* __restrict__ group_vec,
    const float* __restrict__ Wp1, const float* __restrict__ bp1,
    const float* __restrict__ Wp2, const float* __restrict__ bp2,
    const float* __restrict__ Ws1, const float* __restrict__ bs1,
    const float* __restrict__ Ws2, const float* __restrict__ bs2)
{
    extern __shared__ char smc[];
    __nv_bfloat16* msHi  = (__nv_bfloat16*)(smc + MS_HI);
    __nv_bfloat16* msLo  = (__nv_bfloat16*)(smc + MS_LO);
    __nv_bfloat16* hPhi  = (__nv_bfloat16*)(smc + HP_HI);
    __nv_bfloat16* hPlo  = (__nv_bfloat16*)(smc + HP_LO);
    __nv_bfloat16* hShi  = (__nv_bfloat16*)(smc + HS_HI);
    __nv_bfloat16* hSlo  = (__nv_bfloat16*)(smc + HS_LO);
    __nv_bfloat16* w1pH  = (__nv_bfloat16*)(smc + W1P_HI);
    __nv_bfloat16* w1pL  = (__nv_bfloat16*)(smc + W1P_LO);
    __nv_bfloat16* w1sH  = (__nv_bfloat16*)(smc + W1S_HI);
    __nv_bfloat16* w1sL  = (__nv_bfloat16*)(smc + W1S_LO);
    __nv_bfloat16* w2pH  = (__nv_bfloat16*)(smc + W2P_HI);
    __nv_bfloat16* w2pL  = (__nv_bfloat16*)(smc + W2P_LO);
    __nv_bfloat16* w2sH  = (__nv_bfloat16*)(smc + W2S_HI);
    __nv_bfloat16* w2sL  = (__nv_bfloat16*)(smc + W2S_LO);
    int*   nS   = (int*)(smc + MK_NS);
    int*   gS   = (int*)(smc + MK_GS);
    float* uS   = (float*)(smc + MK_US);
    float* bp1s = (float*)(smc + MK_BP1);
    float* bs1s = (float*)(smc + MK_BS1);
    float* bp2s = (float*)(smc + MK_BP2);
    float* bs2s = (float*)(smc + MK_BS2);
    float* spS  = (float*)(smc + MS_HI);
    float* svS  = (float*)(smc + HP_HI);

    const int t = threadIdx.x;
    const int lane = t & 31, wid = t >> 5;
    const int wm = wid & 1, wn = wid >> 1;

    for (int idx = t; idx < 64 * 128; idx += ETB) {
        int n = idx & 63, k = idx >> 6;
        float vp = Wp1[k * 64 + n], vs = Ws1[k * 64 + n];
        __nv_bfloat16 h = __float2bfloat16(vp);
        w1pH[n * 136 + k] = h;
        w1pL[n * 136 + k] = __float2bfloat16(vp - __bfloat162float(h));
        h = __float2bfloat16(vs);
        w1sH[n * 136 + k] = h;
        w1sL[n * 136 + k] = __float2bfloat16(vs - __bfloat162float(h));
    }
    for (int idx = t; idx < 128 * 64; idx += ETB) {
        int n = idx & 127, k = idx >> 7;
        float vp = Wp2[k * 128 + n], vs = Ws2[k * 128 + n];
        __nv_bfloat16 h = __float2bfloat16(vp);
        w2pH[n * 72 + k] = h;
        w2pL[n * 72 + k] = __float2bfloat16(vp - __bfloat162float(h));
        h = __float2bfloat16(vs);
        w2sH[n * 72 + k] = h;
        w2sL[n * 72 + k] = __float2bfloat16(vs - __bfloat162float(h));
    }
    if (t < 64)  { bp1s[t] = bp1[t]; bs1s[t] = bs1[t]; }
    if (t < 128) { bp2s[t] = bp2[t]; bs2s[t] = bs2[t]; }

    const int nTiles = EE / 64;
    for (int tile = blockIdx.x; tile < nTiles; tile += gridDim.x) {
        const int e0 = tile * 64;
        __syncthreads();

        {
            int r = t >> 3, sub = t & 7;
            int e = e0 + r;
            int n = node_idx[e], g = group_idx[e];
            if (sub == 0) { nS[r] = n; gS[r] = g; }
            if (t < 192) uS[t] = -edge_vec[(size_t)e0 * 3 + t];
            int c0 = sub * 16;
            float s = 0.f;
            #pragma unroll
            for (int j = 0; j < 4; j++) {
                float4 q4 = *(const float4*)&g_q[(size_t)n * 128 + c0 + j * 4];
                float4 k4 = *(const float4*)&g_k[(size_t)g * 128 + c0 + j * 4];
                float4 a4 = *(const float4*)&edge_attr[(size_t)e * 128 + c0 + j * 4];
                s += q4.x * k4.x * a4.x + q4.y * k4.y * a4.y
                   + q4.z * k4.z * a4.z + q4.w * k4.w * a4.w;
            }
            float attn = silu_f(s * 0.25f);
            #pragma unroll
            for (int j = 0; j < 4; j++) {
                float4 v4 = *(const float4*)&g_val[(size_t)g * 128 + c0 + j * 4];
                float4 m = make_float4(v4.x * attn, v4.y * attn, v4.z * attn, v4.w * attn);
                red_v4(&g_msn[(size_t)n * 128 + c0 + j * 4], m);
                uint32_t h0, l0, h1, l1;
                split2(m.x, m.y, h0, l0);
                split2(m.z, m.w, h1, l1);
                int bidx = r * 136 + c0 + j * 4;
                *(uint32_t*)&msHi[bidx] = h0;     *(uint32_t*)&msHi[bidx + 2] = h1;
                *(uint32_t*)&msLo[bidx] = l0;     *(uint32_t*)&msLo[bidx + 2] = l1;
            }
        }
        __syncthreads();

        {
            float accP[2][4], accS[2][4];
            #pragma unroll
            for (int mf = 0; mf < 2; mf++)
                #pragma unroll
                for (int q = 0; q < 4; q++) { accP[mf][q] = 0.f; accS[mf][q] = 0.f; }
            const int rB = wm * 32 + (lane >> 2);
            const int klo = (lane & 3) * 2;
            #pragma unroll
            for (int ks = 0; ks < 8; ks++) {
                uint32_t ahi[2][4], alo[2][4];
                #pragma unroll
                for (int mf = 0; mf < 2; mf++)
                    #pragma unroll
                    for (int q = 0; q < 4; q++) {
                        int row = rB + mf * 16 + (q & 1) * 8;
                        int kk = ks * 16 + klo + (q >> 1) * 8;
                        ahi[mf][q] = *(const uint32_t*)&msHi[row * 136 + kk];
                        alo[mf][q] = *(const uint32_t*)&msLo[row * 136 + kk];
                    }
                int nIdx = wn * 8 + (lane >> 2);
                int kb = ks * 16 + klo;
                uint32_t ph0 = *(const uint32_t*)&w1pH[nIdx * 136 + kb];
                uint32_t ph1 = *(const uint32_t*)&w1pH[nIdx * 136 + kb + 8];
                uint32_t pl0 = *(const uint32_t*)&w1pL[nIdx * 136 + kb];
                uint32_t pl1 = *(const uint32_t*)&w1pL[nIdx * 136 + kb + 8];
                uint32_t sh0 = *(const uint32_t*)&w1sH[nIdx * 136 + kb];
                uint32_t sh1 = *(const uint32_t*)&w1sH[nIdx * 136 + kb + 8];
                uint32_t sl0 = *(const uint32_t*)&w1sL[nIdx * 136 + kb];
                uint32_t sl1 = *(const uint32_t*)&w1sL[nIdx * 136 + kb + 8];
                #pragma unroll
                for (int mf = 0; mf < 2; mf++) {
                    mma_bf16(accP[mf], ahi[mf], ph0, ph1);
                    mma_bf16(accP[mf], ahi[mf], pl0, pl1);
                    mma_bf16(accP[mf], alo[mf], ph0, ph1);
                    mma_bf16(accS[mf], ahi[mf], sh0, sh1);
                    mma_bf16(accS[mf], ahi[mf], sl0, sl1);
                    mma_bf16(accS[mf], alo[mf], sh0, sh1);
                }
            }
            int cb = wn * 8 + (lane & 3) * 2;
            float b0p = bp1s[cb], b1p = bp1s[cb + 1];
            float b0s = bs1s[cb], b1s = bs1s[cb + 1];
            #pragma unroll
            for (int mf = 0; mf < 2; mf++) {
                int row = wm * 32 + mf * 16 + (lane >> 2);
                uint32_t h, l;
                split2(silu_f(accP[mf][0] + b0p), silu_f(accP[mf][1] + b1p), h, l);
                *(uint32_t*)&hPhi[row * 72 + cb] = h;  *(uint32_t*)&hPlo[row * 72 + cb] = l;
                split2(silu_f(accP[mf][2] + b0p), silu_f(accP[mf][3] + b1p), h, l);
                *(uint32_t*)&hPhi[(row + 8) * 72 + cb] = h;  *(uint32_t*)&hPlo[(row + 8) * 72 + cb] = l;
                split2(silu_f(accS[mf][0] + b0s), silu_f(accS[mf][1] + b1s), h, l);
                *(uint32_t*)&hShi[row * 72 + cb] = h;  *(uint32_t*)&hSlo[row * 72 + cb] = l;
                split2(silu_f(accS[mf][2] + b0s), silu_f(accS[mf][3] + b1s), h, l);
                *(uint32_t*)&hShi[(row + 8) * 72 + cb] = h;  *(uint32_t*)&hSlo[(row + 8) * 72 + cb] = l;
            }
        }
        __syncthreads();

        float acc2P[2][2][4], acc2S[2][2][4];
        #pragma unroll
        for (int mf = 0; mf < 2; mf++)
            #pragma unroll
            for (int j = 0; j < 2; j++)
                #pragma unroll
                for (int q = 0; q < 4; q++) { acc2P[mf][j][q] = 0.f; acc2S[mf][j][q] = 0.f; }
        {
            const int rB = wm * 32 + (lane >> 2);
            const int klo = (lane & 3) * 2;
            #pragma unroll
            for (int ks = 0; ks < 4; ks++) {
                uint32_t aPh[2][4], aPl[2][4], aSh[2][4], aSl[2][4];
                #pragma unroll
                for (int mf = 0; mf < 2; mf++)
                    #pragma unroll
                    for (int q = 0; q < 4; q++) {
                        int row = rB + mf * 16 + (q & 1) * 8;
                        int kk = ks * 16 + klo + (q >> 1) * 8;
                        int off = row * 72 + kk;
                        aPh[mf][q] = *(const uint32_t*)&hPhi[off];
                        aPl[mf][q] = *(const uint32_t*)&hPlo[off];
                        aSh[mf][q] = *(const uint32_t*)&hShi[off];
                        aSl[mf][q] = *(const uint32_t*)&hSlo[off];
                    }
                #pragma unroll
                for (int j = 0; j < 2; j++) {
                    int nIdx = wn * 16 + j * 8 + (lane >> 2);
                    int kb = ks * 16 + klo;
                    uint32_t ph0 = *(const uint32_t*)&w2pH[nIdx * 72 + kb];
                    uint32_t ph1 = *(const uint32_t*)&w2pH[nIdx * 72 + kb + 8];
                    uint32_t pl0 = *(const uint32_t*)&w2pL[nIdx * 72 + kb];
                    uint32_t pl1 = *(const uint32_t*)&w2pL[nIdx * 72 + kb + 8];
                    uint32_t sh0 = *(const uint32_t*)&w2sH[nIdx * 72 + kb];
                    uint32_t sh1 = *(const uint32_t*)&w2sH[nIdx * 72 + kb + 8];
                    uint32_t sl0 = *(const uint32_t*)&w2sL[nIdx * 72 + kb];
                    uint32_t sl1 = *(const uint32_t*)&w2sL[nIdx * 72 + kb + 8];
                    #pragma unroll
                    for (int mf = 0; mf < 2; mf++) {
                        mma_bf16(acc2P[mf][j], aPh[mf], ph0, ph1);
                        mma_bf16(acc2P[mf][j], aPh[mf], pl0, pl1);
                        mma_bf16(acc2P[mf][j], aPl[mf], ph0, ph1);
                        mma_bf16(acc2S[mf][j], aSh[mf], sh0, sh1);
                        mma_bf16(acc2S[mf][j], aSh[mf], sl0, sl1);
                        mma_bf16(acc2S[mf][j], aSl[mf], sh0, sh1);
                    }
                }
            }
        }
        __syncthreads();

        #pragma unroll
        for (int mf = 0; mf < 2; mf++) {
            #pragma unroll
            for (int j = 0; j < 2; j++) {
                int row = wm * 32 + mf * 16 + (lane >> 2);
                int cb = wn * 16 + j * 8 + (lane & 3) * 2;
                float b0p = bp2s[cb], b1p = bp2s[cb + 1];
                float b0s = bs2s[cb], b1s = bs2s[cb + 1];
                *(float2*)&spS[row * 132 + cb] =
                    make_float2(acc2P[mf][j][0] + b0p, acc2P[mf][j][1] + b1p);
                *(float2*)&spS[(row + 8) * 132 + cb] =
                    make_float2(acc2P[mf][j][2] + b0p, acc2P[mf][j][3] + b1p);
                *(float2*)&svS[row * 132 + cb] =
                    make_float2(acc2S[mf][j][0] + b0s, acc2S[mf][j][1] + b1s);
                *(float2*)&svS[(row + 8) * 132 + cb] =
                    make_float2(acc2S[mf][j][2] + b0s, acc2S[mf][j][3] + b1s);
            }
        }
        __syncthreads();

        #pragma unroll
        for (int i = 0; i < 12; i++) {
            int flat = t + i * ETB;
            int r = flat / 96;
            int rem = flat - r * 96;
            int d = rem >> 5, c = rem & 31;
            float4 sp = *(float4*)&spS[r * 132 + c * 4];
            float4 sv = *(float4*)&svS[r * 132 + c * 4];
            float u = uS[r * 3 + d];
            int gg = gS[r], nn = nS[r];
            float4 gv = *(const float4*)&group_vec[((size_t)gg * 3 + d) * 128 + c * 4];
            float4 mv = make_float4(sp.x * u + sv.x * gv.x, sp.y * u + sv.y * gv.y,
                                    sp.z * u + sv.z * gv.z, sp.w * u + sv.w * gv.w);
            red_v4(&g_mv[((size_t)nn * 3 + d) * 128 + c * 4], mv);
        }
    }
}

// ---------------- launch ----------------
static inline int gsz(int R) { int nT = (R + 127) >> 7; return nT < 148 ? nT : 148; }
static inline int gsz32(int R) { int nT = (R + 31) >> 5; return nT < 148 ? nT : 148; }

extern "C" void kernel_launch(void* const* d_in, const int* in_sizes, int n_in,
                              void* d_out, int out_size) {
    const int*   node_idx        = (const int*)d_in[0];
    const int*   group_idx       = (const int*)d_in[1];
    const float* node_embedding  = (const float*)d_in[2];
    const float* node_vec        = (const float*)d_in[3];
    const float* group_embedding = (const float*)d_in[4];
    const float* group_vec       = (const float*)d_in[5];
    const float* edge_attr       = (const float*)d_in[6];
    const float* edge_vec        = (const float*)d_in[8];
    const float* Wq  = (const float*)d_in[9];  const float* bq  = (const float*)d_in[10];
    const float* Wk  = (const float*)d_in[11]; const float* bk  = (const float*)d_in[12];
    const float* Wvl = (const float*)d_in[13]; const float* bvl = (const float*)d_in[14];
    const float* Wp1 = (const float*)d_in[15]; const float* bp1 = (const float*)d_in[16];
    const float* Wp2 = (const float*)d_in[17]; const float* bp2 = (const float*)d_in[18];
    const float* Ws1 = (const float*)d_in[19]; const float* bs1 = (const float*)d_in[20];
    const float* Ws2 = (const float*)d_in[21]; const float* bs2 = (const float*)d_in[22];
    const float* L0  = (const float*)d_in[23];
    const float* L1  = (const float*)d_in[24];
    const float* L2  = (const float*)d_in[25];
    const float* L3  = (const float*)d_in[26];
    const float* L4  = (const float*)d_in[27];
    const float* L5  = (const float*)d_in[28];

    float* dx = (float*)d_out;
    float* dv = (float*)d_out + (size_t)NN * 128;

    const int SM_G  = 208896;
    const int SM_W2 = 16896 + 2 * 67584;   // 152064
    const int SM_W3 = 16896 + 3 * 67584;   // 219648
    cudaFuncSetAttribute(gemm_mma<false, 0, 2>, cudaFuncAttributeMaxDynamicSharedMemorySize, SM_G);
    cudaFuncSetAttribute(gemm_mma<false, 1, 2>, cudaFuncAttributeMaxDynamicSharedMemorySize, SM_G);
    cudaFuncSetAttribute(gemm_mma<true, 2, 1>,  cudaFuncAttributeMaxDynamicSharedMemorySize, SM_G);
    cudaFuncSetAttribute(gemmNW<2>, cudaFuncAttributeMaxDynamicSharedMemorySize, SM_W2);
    cudaFuncSetAttribute(gemmNW<3>, cudaFuncAttributeMaxDynamicSharedMemorySize, SM_W3);
    cudaFuncSetAttribute(edge_mega, cudaFuncAttributeMaxDynamicSharedMemorySize, MEGA_SMEM);

    float *p_q, *p_k, *p_val, *p_msn, *p_A, *p_B, *p_mv;
    cudaGetSymbolAddress((void**)&p_q, g_q);
    cudaGetSymbolAddress((void**)&p_k, g_k);
    cudaGetSymbolAddress((void**)&p_val, g_val);
    cudaGetSymbolAddress((void**)&p_msn, g_msn);
    cudaGetSymbolAddress((void**)&p_A, g_A);
    cudaGetSymbolAddress((void**)&p_B, g_B4);
    cudaGetSymbolAddress((void**)&p_mv, g_mv);

    cudaMemsetAsync(p_msn, 0, sizeof(float) * (size_t)NN * 128, 0);
    cudaMemsetAsync(p_mv,  0, sizeof(float) * (size_t)NN * 384, 0);

    // q (R5 config) ; k+val merged (one pass over group_embedding)
    gemm_mma<false, 0, 2><<<gsz(NN), 512, SM_G>>>(node_embedding, Wq, bq, nullptr, p_q, nullptr, nullptr, NN);
    gemmNW<2><<<gsz32(GG), 256, SM_W2>>>(group_embedding, Wk, Wvl, nullptr,
                                         bk, bvl, nullptr,
                                         p_k, p_val, nullptr, GG);

    // fused edge pipeline (R5-exact)
    edge_mega<<<148, ETB, MEGA_SMEM>>>(node_idx, group_idx, edge_attr, edge_vec, group_vec,
                                       Wp1, bp1, Wp2, bp2, Ws1, bs1, Ws2, bs2);

    // node-side triple: A = msn@L0, B = msn@L4, dx = msn@L5 (measured 126us)
    gemmNW<3><<<gsz32(NN), 256, SM_W3>>>(p_msn, L0, L4, L5,
                                         nullptr, nullptr, nullptr,
                                         p_A, p_B, dx, NN);

    // dv = g_mv + A[n] * (nv@L1)   (R5 config)
    gemm_mma<false, 1, 2><<<gsz(3 * NN), 512, SM_G>>>(node_vec, L1, nullptr, nullptr, dv, p_mv, p_A, 3 * NN);

    // dx += sum_d (nv@L2)*(nv@L3)*B[n]   (R5 config)
    gemm_mma<true, 2, 1><<<gsz(3 * NN), 512, SM_G>>>(node_vec, L2, nullptr, L3, dx, nullptr, p_B, 3 * NN);
}